// round 10
// baseline (speedup 1.0000x reference)
#include <cuda_runtime.h>
#include <cuda_bf16.h>
#include <cstdint>
#include <math.h>

// Problem dims (fixed by dataset)
#define TSTEPS 16
#define NNODES 4096
#define RDIM   256
#define CDIM   32

// Scratch (static device globals — no allocation)
__device__ float g_MzT[64 * RDIM * 4];                    // (Wz+Uz) in [k4][r][4]
__device__ float g_MrT[64 * RDIM * 4];                    // (Wr+Ur) in [k4][r][4]
__device__ float g_WhT[64 * RDIM * 4];                    // Wh      in [k4][r][4]
__device__ float g_UhT[64 * RDIM * 4];                    // Uh      in [k4][r][4]
__device__ unsigned short g_Qth[TSTEPS * CDIM * RDIM];    // Q^T hi bf16 [t][n][k]
__device__ unsigned short g_Qtl[TSTEPS * CDIM * RDIM];    // Q^T lo bf16
__device__ unsigned short g_Yth[TSTEPS * CDIM * NNODES];  // Y^T hi bf16 [t][n][k]
__device__ unsigned short g_Ytl[TSTEPS * CDIM * NNODES];  // Y^T lo bf16

// ---------------------------------------------------------------------------
// Small PTX helpers
// ---------------------------------------------------------------------------
__device__ __forceinline__ uint32_t smem_u32(const void* p) {
    uint32_t a;
    asm("{ .reg .u64 t; cvta.to.shared.u64 t, %1; cvt.u32.u64 %0, t; }"
        : "=r"(a) : "l"(p));
    return a;
}
__device__ __forceinline__ uint32_t cvt_bf16x2(float hi, float lo) {
    uint32_t r;
    asm("cvt.rn.bf16x2.f32 %0, %1, %2;" : "=r"(r) : "f"(hi), "f"(lo));
    return r;
}
__device__ __forceinline__ void ldsm4(uint32_t* r, uint32_t a) {
    asm volatile("ldmatrix.sync.aligned.m8n8.x4.shared.b16 {%0,%1,%2,%3}, [%4];"
                 : "=r"(r[0]), "=r"(r[1]), "=r"(r[2]), "=r"(r[3]) : "r"(a));
}
__device__ __forceinline__ void mma16816(float* c, const uint32_t* a,
                                         uint32_t b0, uint32_t b1) {
    asm volatile(
        "mma.sync.aligned.m16n8k16.row.col.f32.bf16.bf16.f32 "
        "{%0,%1,%2,%3}, {%4,%5,%6,%7}, {%8,%9}, {%0,%1,%2,%3};"
        : "+f"(c[0]), "+f"(c[1]), "+f"(c[2]), "+f"(c[3])
        : "r"(a[0]), "r"(a[1]), "r"(a[2]), "r"(a[3]), "r"(b0), "r"(b1));
}
__device__ __forceinline__ float2 ldsf2(uint32_t a) {
    float2 v;
    asm volatile("ld.shared.v2.f32 {%0,%1}, [%2];" : "=f"(v.x), "=f"(v.y) : "r"(a));
    return v;
}
__device__ __forceinline__ void cpasync16(uint32_t s, const void* g) {
    asm volatile("cp.async.cg.shared.global [%0], [%1], 16;" :: "r"(s), "l"(g));
}
__device__ __forceinline__ void cp_commit() {
    asm volatile("cp.async.commit_group;" ::: "memory");
}
// Split fp32 pair -> bf16x2 hi (lower=f.x) + bf16x2 residual lo
__device__ __forceinline__ void split2(float2 f, uint32_t& h, uint32_t& l) {
    h = cvt_bf16x2(f.y, f.x);
    float gx = __uint_as_float(h << 16);
    float gy = __uint_as_float(h & 0xFFFF0000u);
    l = cvt_bf16x2(f.y - gy, f.x - gx);
}

// ---------------------------------------------------------------------------
// Prep: fold z/r gate weight pairs AND repack all 4 GRU matrices into the
// interleaved-transposed layout T[k4][r][0..3] = M[r][4*k4 .. 4*k4+3].
// grid = (4 row-groups, 4 matrices), 256 threads.
// ---------------------------------------------------------------------------
__global__ void __launch_bounds__(256) prep_trans(
    const float* __restrict__ Wz, const float* __restrict__ Uz,
    const float* __restrict__ Wr, const float* __restrict__ Ur,
    const float* __restrict__ Wh, const float* __restrict__ Uh) {
    __shared__ float tile[64][65];
    const int rg  = blockIdx.x;       // row group (64 rows)
    const int mat = blockIdx.y;       // which matrix
    const int tid = threadIdx.x;

    const float *s1, *s2;
    float* dst;
    if (mat == 0)      { s1 = Wz; s2 = Uz; dst = g_MzT; }
    else if (mat == 1) { s1 = Wr; s2 = Ur; dst = g_MrT; }
    else if (mat == 2) { s1 = Wh; s2 = nullptr; dst = g_WhT; }
    else               { s1 = Uh; s2 = nullptr; dst = g_UhT; }

    for (int kc = 0; kc < 4; kc++) {
        #pragma unroll
        for (int i = 0; i < 16; i++) {
            int ii = tid + i * 256;
            int rr = ii >> 6, kk = ii & 63;
            long src = (long)(rg * 64 + rr) * RDIM + kc * 64 + kk;
            float v = s1[src];
            if (s2) v += s2[src];
            tile[rr][kk] = v;
        }
        __syncthreads();
        #pragma unroll
        for (int i = 0; i < 4; i++) {
            int ii = tid + i * 256;
            int rr = ii & 63, k4l = ii >> 6;
            float4 v = make_float4(tile[rr][k4l * 4],     tile[rr][k4l * 4 + 1],
                                   tile[rr][k4l * 4 + 2], tile[rr][k4l * 4 + 3]);
            ((float4*)dst)[(kc * 16 + k4l) * RDIM + rg * 64 + rr] = v;
        }
        __syncthreads();
    }
}

// ---------------------------------------------------------------------------
// GRU evolution of Q [256,32] over 16 steps.
// 16 blocks x 2 columns each; 256 threads = one per output row.
// Transposed-interleaved weights: coalesced LDG.128, q broadcast from smem —
// no reductions, no shuffles, no bank conflicts.
// Emits Q^T bf16 hi/lo (B operand layout for the XQ tensor GEMM).
// ---------------------------------------------------------------------------
__device__ __forceinline__ float dot4(float4 a, float4 b) {
    return a.x * b.x + a.y * b.y + a.z * b.z + a.w * b.w;
}

__global__ void __launch_bounds__(RDIM) gru_kernel(const float* __restrict__ Q0) {
    const int b = blockIdx.x;     // columns 2b, 2b+1
    const int r = threadIdx.x;

    __shared__ float q0s[RDIM], q1s[RDIM], rq0[RDIM], rq1[RDIM];

    q0s[r] = Q0[r * CDIM + 2 * b];
    q1s[r] = Q0[r * CDIM + 2 * b + 1];
    __syncthreads();

    const float4* MzT = (const float4*)g_MzT;
    const float4* MrT = (const float4*)g_MrT;
    const float4* WhT = (const float4*)g_WhT;
    const float4* UhT = (const float4*)g_UhT;

    for (int t = 0; t < TSTEPS; t++) {
        float sz0 = 0.f, sz1 = 0.f, sr0 = 0.f, sr1 = 0.f;
        #pragma unroll 8
        for (int k4 = 0; k4 < 64; k4++) {
            float4 wz = MzT[k4 * RDIM + r];
            float4 wr = MrT[k4 * RDIM + r];
            float4 qa = *(const float4*)&q0s[k4 * 4];
            float4 qb = *(const float4*)&q1s[k4 * 4];
            sz0 += dot4(wz, qa); sz1 += dot4(wz, qb);
            sr0 += dot4(wr, qa); sr1 += dot4(wr, qb);
        }
        float z0  = 1.f / (1.f + expf(-sz0));
        float z1  = 1.f / (1.f + expf(-sz1));
        float rg0 = 1.f / (1.f + expf(-sr0));
        float rg1 = 1.f / (1.f + expf(-sr1));

        rq0[r] = rg0 * q0s[r];
        rq1[r] = rg1 * q1s[r];
        __syncthreads();

        float sh0 = 0.f, sh1 = 0.f;
        #pragma unroll 8
        for (int k4 = 0; k4 < 64; k4++) {
            float4 wh = WhT[k4 * RDIM + r];
            float4 uh = UhT[k4 * RDIM + r];
            float4 qa = *(const float4*)&q0s[k4 * 4];
            float4 qb = *(const float4*)&q1s[k4 * 4];
            float4 ra = *(const float4*)&rq0[k4 * 4];
            float4 rb = *(const float4*)&rq1[k4 * 4];
            sh0 += dot4(wh, qa) + dot4(uh, ra);
            sh1 += dot4(wh, qb) + dot4(uh, rb);
        }
        float h0  = tanhf(sh0);
        float h1  = tanhf(sh1);
        float qn0 = (1.f - z0) * q0s[r] + z0 * h0;
        float qn1 = (1.f - z1) * q1s[r] + z1 * h1;

        __syncthreads();
        q0s[r] = qn0;
        q1s[r] = qn1;

        #pragma unroll
        for (int j = 0; j < 2; j++) {
            float qn = j ? qn1 : qn0;
            uint32_t ph = cvt_bf16x2(0.f, qn);
            float    hf = __uint_as_float(ph << 16);
            uint32_t pl = cvt_bf16x2(0.f, qn - hf);
            long qoff = ((long)t * CDIM + 2 * b + j) * RDIM + r;
            g_Qth[qoff] = (unsigned short)(ph & 0xFFFFu);
            g_Qtl[qoff] = (unsigned short)(pl & 0xFFFFu);
        }
        __syncthreads();
    }
}

// ---------------------------------------------------------------------------
// XQ: Y_t = X_t @ Q_t (tensor, R8-proven static-smem register-staged kernel).
// D[128m x 32n], K=256 in 4 chunks of 64. 4 warps x (32m x 32n).
// X fp32 -> bf16 hi/lo in registers -> smem; Q^T bf16 hi/lo via ldmatrix.
// Epilogue: transpose through smem, emit Y^T bf16 hi/lo [t][n][m].
// ---------------------------------------------------------------------------
#define APAD 72
#define SM_AH 0
#define SM_AL (128 * APAD * 2)
#define SM_BH (2 * 128 * APAD * 2)
#define SM_BL (2 * 128 * APAD * 2 + 32 * APAD * 2)
#define SM_TOT (2 * 128 * APAD * 2 + 2 * 32 * APAD * 2)

__global__ void __launch_bounds__(128, 3) xq_mma(
    const float* __restrict__ Abase,
    const unsigned short* __restrict__ Bhb,
    const unsigned short* __restrict__ Blb,
    unsigned short* __restrict__ OTh,
    unsigned short* __restrict__ OTl) {

    constexpr int NC = 4;
    constexpr int K  = NC * 64;   // 256
    __shared__ __align__(16) unsigned char smem[SM_TOT];

    const int tid  = threadIdx.x;
    const int wid  = tid >> 5;
    const int lane = tid & 31;
    const int t    = blockIdx.y;
    const int mb   = blockIdx.x;

    const float* Ap = Abase + ((long)t * NNODES + (long)mb * 128) * K;
    const unsigned short* Bgh = Bhb + (long)t * CDIM * K;
    const unsigned short* Bgl = Blb + (long)t * CDIM * K;

    int aoff[16];
    int smA[16];   // byte offsets
    #pragma unroll
    for (int i = 0; i < 16; i++) {
        int idx = tid + i * 128;
        int m = idx >> 4, qd = idx & 15;
        aoff[i] = m * K + qd * 4;
        smA[i]  = (m * APAD + qd * 4) * 2;
    }
    int boffB[2], smB[2];
    #pragma unroll
    for (int i = 0; i < 2; i++) {
        int idx = tid + i * 128;
        int bn = idx >> 3, bq = idx & 7;
        boffB[i] = bn * K + bq * 8;     // ushort units
        smB[i]   = (bn * APAD + bq * 8) * 2;
    }

    const uint32_t sb = smem_u32(smem);
    const int g = lane >> 3;
    const int rowA = wid * 32 + (lane & 7) + ((g & 1) ? 8 : 0);
    const uint32_t offA0 = rowA * (APAD * 2) + (g >> 1) * 16;
    const uint32_t offA1 = offA0 + 16 * (APAD * 2);
    const int rowB = (lane & 7) + ((g >> 1) ? 8 : 0);
    const uint32_t offB0 = rowB * (APAD * 2) + (g & 1) * 16;
    const uint32_t offB1 = offB0 + 16 * (APAD * 2);

    float acc[2][4][4];
    #pragma unroll
    for (int ti = 0; ti < 2; ti++)
        #pragma unroll
        for (int j = 0; j < 4; j++)
            #pragma unroll
            for (int i = 0; i < 4; i++) acc[ti][j][i] = 0.f;

    float4 aR[16];
    uint4  bhR[2], blR[2];

    auto fetch = [&](int c) {
        const float* ap = Ap + c * 64;
        #pragma unroll
        for (int i = 0; i < 16; i++) aR[i] = *(const float4*)(ap + aoff[i]);
        #pragma unroll
        for (int i = 0; i < 2; i++) {
            bhR[i] = *(const uint4*)(Bgh + boffB[i] + c * 64);
            blR[i] = *(const uint4*)(Bgl + boffB[i] + c * 64);
        }
    };
    auto stage = [&]() {
        #pragma unroll
        for (int i = 0; i < 16; i++) {
            float4 f = aR[i];
            uint32_t h01 = cvt_bf16x2(f.y, f.x);
            uint32_t h23 = cvt_bf16x2(f.w, f.z);
            float g0 = __uint_as_float(h01 << 16);
            float g1 = __uint_as_float(h01 & 0xFFFF0000u);
            float g2 = __uint_as_float(h23 << 16);
            float g3 = __uint_as_float(h23 & 0xFFFF0000u);
            uint32_t l01 = cvt_bf16x2(f.y - g1, f.x - g0);
            uint32_t l23 = cvt_bf16x2(f.w - g3, f.z - g2);
            *(uint2*)(smem + SM_AH + smA[i]) = make_uint2(h01, h23);
            *(uint2*)(smem + SM_AL + smA[i]) = make_uint2(l01, l23);
        }
        #pragma unroll
        for (int i = 0; i < 2; i++) {
            *(uint4*)(smem + SM_BH + smB[i]) = bhR[i];
            *(uint4*)(smem + SM_BL + smB[i]) = blR[i];
        }
    };

    fetch(0);
    stage();
    __syncthreads();

    for (int c = 0; c < NC; c++) {
        if (c + 1 < NC) fetch(c + 1);

        #pragma unroll
        for (int ks = 0; ks < 4; ks++) {
            uint32_t ah0[4], al0[4], ah1[4], al1[4], bh[8], bl[8];
            ldsm4(ah0, sb + SM_AH + offA0 + ks * 32);
            ldsm4(ah1, sb + SM_AH + offA1 + ks * 32);
            ldsm4(al0, sb + SM_AL + offA0 + ks * 32);
            ldsm4(al1, sb + SM_AL + offA1 + ks * 32);
            ldsm4(bh,     sb + SM_BH + offB0 + ks * 32);
            ldsm4(bh + 4, sb + SM_BH + offB1 + ks * 32);
            ldsm4(bl,     sb + SM_BL + offB0 + ks * 32);
            ldsm4(bl + 4, sb + SM_BL + offB1 + ks * 32);
            #pragma unroll
            for (int j = 0; j < 4; j++) {
                mma16816(acc[0][j], ah0, bh[2 * j], bh[2 * j + 1]);
                mma16816(acc[0][j], ah0, bl[2 * j], bl[2 * j + 1]);
                mma16816(acc[0][j], al0, bh[2 * j], bh[2 * j + 1]);
                mma16816(acc[1][j], ah1, bh[2 * j], bh[2 * j + 1]);
                mma16816(acc[1][j], ah1, bl[2 * j], bl[2 * j + 1]);
                mma16816(acc[1][j], al1, bh[2 * j], bh[2 * j + 1]);
            }
        }
        __syncthreads();
        if (c + 1 < NC) {
            stage();
            __syncthreads();
        }
    }

    // Epilogue: transpose through smem, split bf16 hi/lo, store [t][n][m]
    const int cg = lane >> 2;
    const int tc = (lane & 3) * 2;
    float* S = (float*)smem;     // [32][132] fp32 (smem reused)
    #pragma unroll
    for (int ti = 0; ti < 2; ti++) {
        int m = wid * 32 + ti * 16 + cg;
        #pragma unroll
        for (int j = 0; j < 4; j++) {
            int n = j * 8 + tc;
            S[n * 132 + m]           = acc[ti][j][0];
            S[(n + 1) * 132 + m]     = acc[ti][j][1];
            S[n * 132 + m + 8]       = acc[ti][j][2];
            S[(n + 1) * 132 + m + 8] = acc[ti][j][3];
        }
    }
    __syncthreads();
    const int n  = tid >> 2;
    const int ms = (tid & 3) * 32;
    float v[32];
    #pragma unroll
    for (int i = 0; i < 8; i++)
        *(float4*)&v[i * 4] = *(const float4*)&S[n * 132 + ms + i * 4];
    uint32_t hp[16], lp[16];
    #pragma unroll
    for (int i = 0; i < 16; i++) {
        hp[i] = cvt_bf16x2(v[2 * i + 1], v[2 * i]);
        float g0 = __uint_as_float(hp[i] << 16);
        float g1 = __uint_as_float(hp[i] & 0xFFFF0000u);
        lp[i] = cvt_bf16x2(v[2 * i + 1] - g1, v[2 * i] - g0);
    }
    long ooff = ((long)t * CDIM + n) * NNODES + mb * 128 + ms;  // ushort units
    #pragma unroll
    for (int i = 0; i < 4; i++) {
        *(uint4*)(OTh + ooff + i * 8) =
            make_uint4(hp[4 * i], hp[4 * i + 1], hp[4 * i + 2], hp[4 * i + 3]);
        *(uint4*)(OTl + ooff + i * 8) =
            make_uint4(lp[4 * i], lp[4 * i + 1], lp[4 * i + 2], lp[4 * i + 3]);
    }
}

// ---------------------------------------------------------------------------
// AY: out_t = relu(A_t @ Y_t) (R9-measured cp.async kernel, 210us).
// A fp32 cp.async'ed (double-buffered), converted to bf16 hi/lo fragments at
// load time from smem; B bf16 hi/lo via ldmatrix. 3 split-precision terms.
// ---------------------------------------------------------------------------
#define AFP 72                              // fp32 pitch for A smem
#define BPD 72                              // bf16 pitch for B smem
#define ASTG (128 * AFP * 4)                // 36864 B per A stage
#define BSTG (32 * BPD * 2)                 // 4608 B per B stage
#define OFF_A(s)  ((s) * ASTG)
#define OFF_BH(s) (2 * ASTG + (s) * BSTG)
#define OFF_BL(s) (2 * ASTG + 2 * BSTG + (s) * BSTG)
#define SMEM_BYTES (2 * ASTG + 4 * BSTG)    // 92160 B

__global__ void __launch_bounds__(128, 2) ay_mma(
    const float* __restrict__ Abase,
    const unsigned short* __restrict__ Bhb,
    const unsigned short* __restrict__ Blb,
    float* __restrict__ Out) {

    constexpr int NC = 64;
    constexpr int K  = NC * 64;   // 4096
    extern __shared__ __align__(16) unsigned char smem[];
    const uint32_t sb = smem_u32(smem);

    const int tid  = threadIdx.x;
    const int wid  = tid >> 5;
    const int lane = tid & 31;
    const int t    = blockIdx.y;
    const int mb   = blockIdx.x;

    const float* Ap = Abase + ((long)t * NNODES + (long)mb * 128) * K;
    const unsigned short* Bgh = Bhb + (long)t * CDIM * K;
    const unsigned short* Bgl = Blb + (long)t * CDIM * K;

    // ldmatrix B lane offsets (byte)
    const int g = lane >> 3;
    const int rowB = (lane & 7) + ((g >> 1) ? 8 : 0);
    const uint32_t offB0 = rowB * (BPD * 2) + (g & 1) * 16;
    const uint32_t offB1 = offB0 + 16 * (BPD * 2);

    // A fragment lane offsets (fp32 smem)
    const int g4 = lane >> 2;
    const int t2 = (lane & 3) * 2;

    float acc[2][4][4];
    #pragma unroll
    for (int ti = 0; ti < 2; ti++)
        #pragma unroll
        for (int j = 0; j < 4; j++)
            #pragma unroll
            for (int i = 0; i < 4; i++) acc[ti][j][i] = 0.f;

    auto load_async = [&](int c, int s) {
        const float* ap = Ap + c * 64;
        #pragma unroll
        for (int i = 0; i < 16; i++) {
            int idx = tid + i * 128;
            int m = idx >> 4, j = idx & 15;
            cpasync16(sb + OFF_A(s) + (m * AFP + j * 4) * 4,
                      ap + (long)m * K + j * 4);
        }
        #pragma unroll
        for (int i = 0; i < 2; i++) {
            int idx = tid + i * 128;
            int n = idx >> 3, jj = idx & 7;
            long go = (long)n * K + c * 64 + jj * 8;
            uint32_t so = (n * BPD + jj * 8) * 2;
            cpasync16(sb + OFF_BH(s) + so, Bgh + go);
            cpasync16(sb + OFF_BL(s) + so, Bgl + go);
        }
        cp_commit();
    };

    auto compute = [&](int s) {
        const uint32_t aBase = sb + OFF_A(s);
        const uint32_t bhB   = sb + OFF_BH(s);
        const uint32_t blB   = sb + OFF_BL(s);
        #pragma unroll
        for (int ks = 0; ks < 4; ks++) {
            uint32_t bh[8], bl[8];
            ldsm4(bh,     bhB + offB0 + ks * 32);
            ldsm4(bh + 4, bhB + offB1 + ks * 32);
            ldsm4(bl,     blB + offB0 + ks * 32);
            ldsm4(bl + 4, blB + offB1 + ks * 32);
            #pragma unroll
            for (int ti = 0; ti < 2; ti++) {
                uint32_t pa = aBase + (((wid * 32 + ti * 16 + g4) * AFP) + ks * 16 + t2) * 4;
                float2 x0 = ldsf2(pa);
                float2 x1 = ldsf2(pa + 8 * AFP * 4);
                float2 x2 = ldsf2(pa + 32);
                float2 x3 = ldsf2(pa + 8 * AFP * 4 + 32);
                uint32_t ah[4], al[4];
                split2(x0, ah[0], al[0]);
                split2(x1, ah[1], al[1]);
                split2(x2, ah[2], al[2]);
                split2(x3, ah[3], al[3]);
                #pragma unroll
                for (int j = 0; j < 4; j++) {
                    mma16816(acc[ti][j], ah, bh[2 * j], bh[2 * j + 1]);
                    mma16816(acc[ti][j], ah, bl[2 * j], bl[2 * j + 1]);
                    mma16816(acc[ti][j], al, bh[2 * j], bh[2 * j + 1]);
                }
            }
        }
    };

    load_async(0, 0);
    for (int c = 0; c < NC; c++) {
        int buf = c & 1;
        if (c + 1 < NC) {
            load_async(c + 1, buf ^ 1);
            asm volatile("cp.async.wait_group 1;" ::: "memory");
        } else {
            asm volatile("cp.async.wait_group 0;" ::: "memory");
        }
        __syncthreads();
        compute(buf);
        __syncthreads();
    }

    // Epilogue: relu + direct store [t][m][n]
    const int cg = lane >> 2;
    const int tc = (lane & 3) * 2;
    #pragma unroll
    for (int ti = 0; ti < 2; ti++) {
        const long row0 = (long)t * NNODES + mb * 128 + wid * 32 + ti * 16 + cg;
        #pragma unroll
        for (int j = 0; j < 4; j++) {
            float2 v0, v1;
            v0.x = fmaxf(acc[ti][j][0], 0.f);
            v0.y = fmaxf(acc[ti][j][1], 0.f);
            v1.x = fmaxf(acc[ti][j][2], 0.f);
            v1.y = fmaxf(acc[ti][j][3], 0.f);
            *(float2*)(Out + row0 * CDIM + j * 8 + tc)       = v0;
            *(float2*)(Out + (row0 + 8) * CDIM + j * 8 + tc) = v1;
        }
    }
}

// ---------------------------------------------------------------------------
// Launch: prep(fold+transpose) -> GRU -> XQ (static tensor) -> AY (cp.async)
// ---------------------------------------------------------------------------
extern "C" void kernel_launch(void* const* d_in, const int* in_sizes, int n_in,
                              void* d_out, int out_size) {
    const float* A  = (const float*)d_in[0];   // [1,16,4096,4096]
    const float* X  = (const float*)d_in[1];   // [16,4096,256]
    const float* Q0 = (const float*)d_in[2];   // [256,32]
    const float* Wz = (const float*)d_in[3];
    const float* Uz = (const float*)d_in[4];
    const float* Wr = (const float*)d_in[5];
    const float* Ur = (const float*)d_in[6];
    const float* Wh = (const float*)d_in[7];
    const float* Uh = (const float*)d_in[8];
    float* out = (float*)d_out;                // [16,4096,32]

    void *pQh = nullptr, *pQl = nullptr, *pYh = nullptr, *pYl = nullptr;
    cudaGetSymbolAddress(&pQh, g_Qth);
    cudaGetSymbolAddress(&pQl, g_Qtl);
    cudaGetSymbolAddress(&pYh, g_Yth);
    cudaGetSymbolAddress(&pYl, g_Ytl);

    cudaFuncSetAttribute(ay_mma,
                         cudaFuncAttributeMaxDynamicSharedMemorySize, SMEM_BYTES);

    // 1. Fold gates + repack all weights into transposed-interleaved layout
    prep_trans<<<dim3(4, 4), 256>>>(Wz, Uz, Wr, Ur, Wh, Uh);

    // 2. Evolve Q over 16 steps (16 blocks x 2 columns, reduction-free)
    gru_kernel<<<16, RDIM>>>(Q0);

    // 3. Y_t = X_t @ Q_t (static-smem tensor kernel) -> Y^T bf16 hi/lo
    xq_mma<<<dim3(NNODES / 128, TSTEPS), 128>>>(
        X, (const unsigned short*)pQh, (const unsigned short*)pQl,
        (unsigned short*)pYh, (unsigned short*)pYl);

    // 4. out_t = relu(A_t @ Y_t) (cp.async tensor kernel)
    ay_mma<<<dim3(NNODES / 128, TSTEPS), 128, SMEM_BYTES>>>(
        A, (const unsigned short*)pYh, (const unsigned short*)pYl, out);
}

// round 11
// speedup vs baseline: 1.4126x; 1.4126x over previous
#include <cuda_runtime.h>
#include <cuda_bf16.h>
#include <cstdint>
#include <math.h>

// Problem dims (fixed by dataset)
#define TSTEPS 16
#define NNODES 4096
#define RDIM   256
#define CDIM   32

// Scratch (static device globals — no allocation)
__device__ float g_Mz[RDIM * RDIM];                       // Wz + Uz (row-major)
__device__ float g_Mr[RDIM * RDIM];                       // Wr + Ur (row-major)
__device__ float g_q [CDIM * RDIM];                       // q  in [c][k] layout
__device__ float g_rq[CDIM * RDIM];                       // rq in [c][k] layout
__device__ unsigned g_bar_cnt;                            // grid-sync arrivals (0 at rest)
__device__ unsigned g_bar_gen;                            // grid-sync generation
__device__ unsigned short g_Qth[TSTEPS * CDIM * RDIM];    // Q^T hi bf16 [t][n][k]
__device__ unsigned short g_Qtl[TSTEPS * CDIM * RDIM];    // Q^T lo bf16
__device__ unsigned short g_Yth[TSTEPS * CDIM * NNODES];  // Y^T hi bf16 [t][n][k]
__device__ unsigned short g_Ytl[TSTEPS * CDIM * NNODES];  // Y^T lo bf16

// ---------------------------------------------------------------------------
// Small PTX helpers
// ---------------------------------------------------------------------------
__device__ __forceinline__ uint32_t smem_u32(const void* p) {
    uint32_t a;
    asm("{ .reg .u64 t; cvta.to.shared.u64 t, %1; cvt.u32.u64 %0, t; }"
        : "=r"(a) : "l"(p));
    return a;
}
__device__ __forceinline__ uint32_t cvt_bf16x2(float hi, float lo) {
    uint32_t r;
    asm("cvt.rn.bf16x2.f32 %0, %1, %2;" : "=r"(r) : "f"(hi), "f"(lo));
    return r;
}
__device__ __forceinline__ void ldsm4(uint32_t* r, uint32_t a) {
    asm volatile("ldmatrix.sync.aligned.m8n8.x4.shared.b16 {%0,%1,%2,%3}, [%4];"
                 : "=r"(r[0]), "=r"(r[1]), "=r"(r[2]), "=r"(r[3]) : "r"(a));
}
__device__ __forceinline__ void mma16816(float* c, const uint32_t* a,
                                         uint32_t b0, uint32_t b1) {
    asm volatile(
        "mma.sync.aligned.m16n8k16.row.col.f32.bf16.bf16.f32 "
        "{%0,%1,%2,%3}, {%4,%5,%6,%7}, {%8,%9}, {%0,%1,%2,%3};"
        : "+f"(c[0]), "+f"(c[1]), "+f"(c[2]), "+f"(c[3])
        : "r"(a[0]), "r"(a[1]), "r"(a[2]), "r"(a[3]), "r"(b0), "r"(b1));
}
__device__ __forceinline__ float2 ldsf2(uint32_t a) {
    float2 v;
    asm volatile("ld.shared.v2.f32 {%0,%1}, [%2];" : "=f"(v.x), "=f"(v.y) : "r"(a));
    return v;
}
__device__ __forceinline__ void cpasync16(uint32_t s, const void* g) {
    asm volatile("cp.async.cg.shared.global [%0], [%1], 16;" :: "r"(s), "l"(g));
}
__device__ __forceinline__ void cp_commit() {
    asm volatile("cp.async.commit_group;" ::: "memory");
}
// Split fp32 pair -> bf16x2 hi (lower=f.x) + bf16x2 residual lo
__device__ __forceinline__ void split2(float2 f, uint32_t& h, uint32_t& l) {
    h = cvt_bf16x2(f.y, f.x);
    float gx = __uint_as_float(h << 16);
    float gy = __uint_as_float(h & 0xFFFF0000u);
    l = cvt_bf16x2(f.y - gy, f.x - gx);
}
__device__ __forceinline__ float dot4(float4 a, float4 b) {
    return a.x * b.x + a.y * b.y + a.z * b.z + a.w * b.w;
}

// ---------------------------------------------------------------------------
// Prep: fold z/r gate weight pairs (W@Q + U@Q = (W+U)@Q), row-major out.
// ---------------------------------------------------------------------------
__global__ void prep_fold(const float* __restrict__ Wz, const float* __restrict__ Uz,
                          const float* __restrict__ Wr, const float* __restrict__ Ur) {
    int i = blockIdx.x * blockDim.x + threadIdx.x;
    g_Mz[i] = Wz[i] + Uz[i];
    g_Mr[i] = Wr[i] + Ur[i];
}

// ---------------------------------------------------------------------------
// Software grid barrier: 32 blocks, all guaranteed resident.
// Generation flag read BEFORE arrival (no missed-wakeup); last arriver resets
// the counter, fences, then bumps the generation. Zero net state change per
// barrier -> safe across graph replays.
// ---------------------------------------------------------------------------
#define GRU_NB 32
__device__ __forceinline__ void gsync() {
    __syncthreads();
    if (threadIdx.x == 0) {
        __threadfence();
        unsigned gen = *(volatile unsigned*)&g_bar_gen;
        if (atomicAdd(&g_bar_cnt, 1u) == GRU_NB - 1) {
            g_bar_cnt = 0;
            __threadfence();
            atomicAdd(&g_bar_gen, 1u);
        } else {
            while (*(volatile unsigned*)&g_bar_gen == gen) { }
        }
        __threadfence();
    }
    __syncthreads();
}

// ---------------------------------------------------------------------------
// GRU evolution of Q [256,32] over 16 steps — persistent weights-in-smem.
// 32 blocks x 256 threads; block owns 8 rows of ALL 4 matrices (32 KB smem,
// loaded ONCE). Per step only q/rq (32 KB each) move through L2.
// Thread (w=row-local, c=column) computes output element (r0+w, c) for both
// phases; z survives phase1->phase2 in a register. 2 grid-syncs per step.
// Emits Q^T bf16 hi/lo directly.
// ---------------------------------------------------------------------------
#define QP 260    // q/rq smem pitch (floats): conflict-free LDS.128
#define GRU_SMEM ((4 * 8 * 256 + 2 * 32 * QP) * 4)   // 99328 B

__global__ void __launch_bounds__(256, 1) gru_persist(const float* __restrict__ Q0,
                                                      const float* __restrict__ Whg,
                                                      const float* __restrict__ Uhg) {
    extern __shared__ float sm[];
    float* wz = sm;            // [8][256]
    float* wr = sm + 2048;
    float* wh = sm + 4096;
    float* uh = sm + 6144;
    float* qs = sm + 8192;     // [32][QP]
    float* rs = sm + 8192 + 32 * QP;

    const int tid = threadIdx.x;
    const int w = tid >> 5, c = tid & 31;
    const int r0 = blockIdx.x * 8;

    // Load this block's 8 rows of all 4 matrices into smem (once).
    #pragma unroll
    for (int i = 0; i < 2; i++) {
        int idx = tid + i * 256;          // 512 float4 per matrix
        int row = idx >> 6, j = (idx & 63) * 4;
        long src = (long)(r0 + row) * RDIM + j;
        *(float4*)&wz[row * 256 + j] = *(const float4*)&g_Mz[src];
        *(float4*)&wr[row * 256 + j] = *(const float4*)&g_Mr[src];
        *(float4*)&wh[row * 256 + j] = *(const float4*)&Whg[src];
        *(float4*)&uh[row * 256 + j] = *(const float4*)&Uhg[src];
    }
    // Init q global, transposed [c][k] (block covers its own 8 rows).
    g_q[c * RDIM + r0 + w] = Q0[(r0 + w) * CDIM + c];
    __threadfence();
    gsync();

    for (int t = 0; t < TSTEPS; t++) {
        // Stage q [32][256] -> smem (coalesced float4)
        #pragma unroll
        for (int i = 0; i < 8; i++) {
            int idx = tid + i * 256;      // 2048 float4
            int cc = idx >> 6, j = (idx & 63) * 4;
            *(float4*)&qs[cc * QP + j] = *(const float4*)&g_q[cc * RDIM + j];
        }
        __syncthreads();

        // Phase 1: gates. w-broadcast + q-vector LDS, no reductions.
        float sz = 0.f, sr = 0.f;
        #pragma unroll 4
        for (int k4 = 0; k4 < 64; k4++) {
            float4 a  = *(const float4*)&wz[w * 256 + k4 * 4];
            float4 d  = *(const float4*)&wr[w * 256 + k4 * 4];
            float4 bq = *(const float4*)&qs[c * QP + k4 * 4];
            sz += dot4(a, bq);
            sr += dot4(d, bq);
        }
        float z    = 1.f / (1.f + expf(-sz));
        float rg   = 1.f / (1.f + expf(-sr));
        float qown = qs[c * QP + r0 + w];
        g_rq[c * RDIM + r0 + w] = rg * qown;
        __threadfence();
        gsync();

        // Stage rq
        #pragma unroll
        for (int i = 0; i < 8; i++) {
            int idx = tid + i * 256;
            int cc = idx >> 6, j = (idx & 63) * 4;
            *(float4*)&rs[cc * QP + j] = *(const float4*)&g_rq[cc * RDIM + j];
        }
        __syncthreads();

        // Phase 2: candidate + state update.
        float sh = 0.f;
        #pragma unroll 4
        for (int k4 = 0; k4 < 64; k4++) {
            float4 a  = *(const float4*)&wh[w * 256 + k4 * 4];
            float4 d  = *(const float4*)&uh[w * 256 + k4 * 4];
            float4 bq = *(const float4*)&qs[c * QP + k4 * 4];
            float4 e  = *(const float4*)&rs[c * QP + k4 * 4];
            sh += dot4(a, bq) + dot4(d, e);
        }
        float h  = tanhf(sh);
        float qn = (1.f - z) * qown + z * h;
        g_q[c * RDIM + r0 + w] = qn;

        // Emit Q^T bf16 hi/lo at [t][c][r0+w]
        uint32_t ph = cvt_bf16x2(0.f, qn);
        float    hf = __uint_as_float(ph << 16);
        uint32_t pl = cvt_bf16x2(0.f, qn - hf);
        long qoff = ((long)t * CDIM + c) * RDIM + r0 + w;
        g_Qth[qoff] = (unsigned short)(ph & 0xFFFFu);
        g_Qtl[qoff] = (unsigned short)(pl & 0xFFFFu);
        __threadfence();
        gsync();
    }
}

// ---------------------------------------------------------------------------
// XQ: Y_t = X_t @ Q_t (tensor, static-smem register-staged kernel).
// D[128m x 32n], K=256 in 4 chunks of 64. 4 warps x (32m x 32n).
// X fp32 -> bf16 hi/lo in registers -> smem; Q^T bf16 hi/lo via ldmatrix.
// Epilogue: transpose through smem, emit Y^T bf16 hi/lo [t][n][m].
// ---------------------------------------------------------------------------
#define APAD 72
#define SM_AH 0
#define SM_AL (128 * APAD * 2)
#define SM_BH (2 * 128 * APAD * 2)
#define SM_BL (2 * 128 * APAD * 2 + 32 * APAD * 2)
#define SM_TOT (2 * 128 * APAD * 2 + 2 * 32 * APAD * 2)

__global__ void __launch_bounds__(128, 3) xq_mma(
    const float* __restrict__ Abase,
    const unsigned short* __restrict__ Bhb,
    const unsigned short* __restrict__ Blb,
    unsigned short* __restrict__ OTh,
    unsigned short* __restrict__ OTl) {

    constexpr int NC = 4;
    constexpr int K  = NC * 64;   // 256
    __shared__ __align__(16) unsigned char smem[SM_TOT];

    const int tid  = threadIdx.x;
    const int wid  = tid >> 5;
    const int lane = tid & 31;
    const int t    = blockIdx.y;
    const int mb   = blockIdx.x;

    const float* Ap = Abase + ((long)t * NNODES + (long)mb * 128) * K;
    const unsigned short* Bgh = Bhb + (long)t * CDIM * K;
    const unsigned short* Bgl = Blb + (long)t * CDIM * K;

    int aoff[16];
    int smA[16];   // byte offsets
    #pragma unroll
    for (int i = 0; i < 16; i++) {
        int idx = tid + i * 128;
        int m = idx >> 4, qd = idx & 15;
        aoff[i] = m * K + qd * 4;
        smA[i]  = (m * APAD + qd * 4) * 2;
    }
    int boffB[2], smB[2];
    #pragma unroll
    for (int i = 0; i < 2; i++) {
        int idx = tid + i * 128;
        int bn = idx >> 3, bq = idx & 7;
        boffB[i] = bn * K + bq * 8;     // ushort units
        smB[i]   = (bn * APAD + bq * 8) * 2;
    }

    const uint32_t sb = smem_u32(smem);
    const int g = lane >> 3;
    const int rowA = wid * 32 + (lane & 7) + ((g & 1) ? 8 : 0);
    const uint32_t offA0 = rowA * (APAD * 2) + (g >> 1) * 16;
    const uint32_t offA1 = offA0 + 16 * (APAD * 2);
    const int rowB = (lane & 7) + ((g >> 1) ? 8 : 0);
    const uint32_t offB0 = rowB * (APAD * 2) + (g & 1) * 16;
    const uint32_t offB1 = offB0 + 16 * (APAD * 2);

    float acc[2][4][4];
    #pragma unroll
    for (int ti = 0; ti < 2; ti++)
        #pragma unroll
        for (int j = 0; j < 4; j++)
            #pragma unroll
            for (int i = 0; i < 4; i++) acc[ti][j][i] = 0.f;

    float4 aR[16];
    uint4  bhR[2], blR[2];

    auto fetch = [&](int c) {
        const float* ap = Ap + c * 64;
        #pragma unroll
        for (int i = 0; i < 16; i++) aR[i] = *(const float4*)(ap + aoff[i]);
        #pragma unroll
        for (int i = 0; i < 2; i++) {
            bhR[i] = *(const uint4*)(Bgh + boffB[i] + c * 64);
            blR[i] = *(const uint4*)(Bgl + boffB[i] + c * 64);
        }
    };
    auto stage = [&]() {
        #pragma unroll
        for (int i = 0; i < 16; i++) {
            float4 f = aR[i];
            uint32_t h01 = cvt_bf16x2(f.y, f.x);
            uint32_t h23 = cvt_bf16x2(f.w, f.z);
            float g0 = __uint_as_float(h01 << 16);
            float g1 = __uint_as_float(h01 & 0xFFFF0000u);
            float g2 = __uint_as_float(h23 << 16);
            float g3 = __uint_as_float(h23 & 0xFFFF0000u);
            uint32_t l01 = cvt_bf16x2(f.y - g1, f.x - g0);
            uint32_t l23 = cvt_bf16x2(f.w - g3, f.z - g2);
            *(uint2*)(smem + SM_AH + smA[i]) = make_uint2(h01, h23);
            *(uint2*)(smem + SM_AL + smA[i]) = make_uint2(l01, l23);
        }
        #pragma unroll
        for (int i = 0; i < 2; i++) {
            *(uint4*)(smem + SM_BH + smB[i]) = bhR[i];
            *(uint4*)(smem + SM_BL + smB[i]) = blR[i];
        }
    };

    fetch(0);
    stage();
    __syncthreads();

    for (int c = 0; c < NC; c++) {
        if (c + 1 < NC) fetch(c + 1);

        #pragma unroll
        for (int ks = 0; ks < 4; ks++) {
            uint32_t ah0[4], al0[4], ah1[4], al1[4], bh[8], bl[8];
            ldsm4(ah0, sb + SM_AH + offA0 + ks * 32);
            ldsm4(ah1, sb + SM_AH + offA1 + ks * 32);
            ldsm4(al0, sb + SM_AL + offA0 + ks * 32);
            ldsm4(al1, sb + SM_AL + offA1 + ks * 32);
            ldsm4(bh,     sb + SM_BH + offB0 + ks * 32);
            ldsm4(bh + 4, sb + SM_BH + offB1 + ks * 32);
            ldsm4(bl,     sb + SM_BL + offB0 + ks * 32);
            ldsm4(bl + 4, sb + SM_BL + offB1 + ks * 32);
            #pragma unroll
            for (int j = 0; j < 4; j++) {
                mma16816(acc[0][j], ah0, bh[2 * j], bh[2 * j + 1]);
                mma16816(acc[0][j], ah0, bl[2 * j], bl[2 * j + 1]);
                mma16816(acc[0][j], al0, bh[2 * j], bh[2 * j + 1]);
                mma16816(acc[1][j], ah1, bh[2 * j], bh[2 * j + 1]);
                mma16816(acc[1][j], ah1, bl[2 * j], bl[2 * j + 1]);
                mma16816(acc[1][j], al1, bh[2 * j], bh[2 * j + 1]);
            }
        }
        __syncthreads();
        if (c + 1 < NC) {
            stage();
            __syncthreads();
        }
    }

    // Epilogue: transpose through smem, split bf16 hi/lo, store [t][n][m]
    const int cg = lane >> 2;
    const int tc = (lane & 3) * 2;
    float* S = (float*)smem;     // [32][132] fp32 (smem reused)
    #pragma unroll
    for (int ti = 0; ti < 2; ti++) {
        int m = wid * 32 + ti * 16 + cg;
        #pragma unroll
        for (int j = 0; j < 4; j++) {
            int n = j * 8 + tc;
            S[n * 132 + m]           = acc[ti][j][0];
            S[(n + 1) * 132 + m]     = acc[ti][j][1];
            S[n * 132 + m + 8]       = acc[ti][j][2];
            S[(n + 1) * 132 + m + 8] = acc[ti][j][3];
        }
    }
    __syncthreads();
    const int n  = tid >> 2;
    const int ms = (tid & 3) * 32;
    float v[32];
    #pragma unroll
    for (int i = 0; i < 8; i++)
        *(float4*)&v[i * 4] = *(const float4*)&S[n * 132 + ms + i * 4];
    uint32_t hp[16], lp[16];
    #pragma unroll
    for (int i = 0; i < 16; i++) {
        hp[i] = cvt_bf16x2(v[2 * i + 1], v[2 * i]);
        float g0 = __uint_as_float(hp[i] << 16);
        float g1 = __uint_as_float(hp[i] & 0xFFFF0000u);
        lp[i] = cvt_bf16x2(v[2 * i + 1] - g1, v[2 * i] - g0);
    }
    long ooff = ((long)t * CDIM + n) * NNODES + mb * 128 + ms;  // ushort units
    #pragma unroll
    for (int i = 0; i < 4; i++) {
        *(uint4*)(OTh + ooff + i * 8) =
            make_uint4(hp[4 * i], hp[4 * i + 1], hp[4 * i + 2], hp[4 * i + 3]);
        *(uint4*)(OTl + ooff + i * 8) =
            make_uint4(lp[4 * i], lp[4 * i + 1], lp[4 * i + 2], lp[4 * i + 3]);
    }
}

// ---------------------------------------------------------------------------
// AY: out_t = relu(A_t @ Y_t) (measured 208us cp.async kernel).
// A fp32 cp.async'ed (double-buffered), converted to bf16 hi/lo fragments at
// load time from smem; B bf16 hi/lo via ldmatrix. 3 split-precision terms.
// ---------------------------------------------------------------------------
#define AFP 72                              // fp32 pitch for A smem
#define BPD 72                              // bf16 pitch for B smem
#define ASTG (128 * AFP * 4)                // 36864 B per A stage
#define BSTG (32 * BPD * 2)                 // 4608 B per B stage
#define OFF_A(s)  ((s) * ASTG)
#define OFF_BH(s) (2 * ASTG + (s) * BSTG)
#define OFF_BL(s) (2 * ASTG + 2 * BSTG + (s) * BSTG)
#define SMEM_BYTES (2 * ASTG + 4 * BSTG)    // 92160 B

__global__ void __launch_bounds__(128, 2) ay_mma(
    const float* __restrict__ Abase,
    const unsigned short* __restrict__ Bhb,
    const unsigned short* __restrict__ Blb,
    float* __restrict__ Out) {

    constexpr int NC = 64;
    constexpr int K  = NC * 64;   // 4096
    extern __shared__ __align__(16) unsigned char smem[];
    const uint32_t sb = smem_u32(smem);

    const int tid  = threadIdx.x;
    const int wid  = tid >> 5;
    const int lane = tid & 31;
    const int t    = blockIdx.y;
    const int mb   = blockIdx.x;

    const float* Ap = Abase + ((long)t * NNODES + (long)mb * 128) * K;
    const unsigned short* Bgh = Bhb + (long)t * CDIM * K;
    const unsigned short* Bgl = Blb + (long)t * CDIM * K;

    // ldmatrix B lane offsets (byte)
    const int g = lane >> 3;
    const int rowB = (lane & 7) + ((g >> 1) ? 8 : 0);
    const uint32_t offB0 = rowB * (BPD * 2) + (g & 1) * 16;
    const uint32_t offB1 = offB0 + 16 * (BPD * 2);

    // A fragment lane offsets (fp32 smem)
    const int g4 = lane >> 2;
    const int t2 = (lane & 3) * 2;

    float acc[2][4][4];
    #pragma unroll
    for (int ti = 0; ti < 2; ti++)
        #pragma unroll
        for (int j = 0; j < 4; j++)
            #pragma unroll
            for (int i = 0; i < 4; i++) acc[ti][j][i] = 0.f;

    auto load_async = [&](int c, int s) {
        const float* ap = Ap + c * 64;
        #pragma unroll
        for (int i = 0; i < 16; i++) {
            int idx = tid + i * 128;
            int m = idx >> 4, j = idx & 15;
            cpasync16(sb + OFF_A(s) + (m * AFP + j * 4) * 4,
                      ap + (long)m * K + j * 4);
        }
        #pragma unroll
        for (int i = 0; i < 2; i++) {
            int idx = tid + i * 128;
            int n = idx >> 3, jj = idx & 7;
            long go = (long)n * K + c * 64 + jj * 8;
            uint32_t so = (n * BPD + jj * 8) * 2;
            cpasync16(sb + OFF_BH(s) + so, Bgh + go);
            cpasync16(sb + OFF_BL(s) + so, Bgl + go);
        }
        cp_commit();
    };

    auto compute = [&](int s) {
        const uint32_t aBase = sb + OFF_A(s);
        const uint32_t bhB   = sb + OFF_BH(s);
        const uint32_t blB   = sb + OFF_BL(s);
        #pragma unroll
        for (int ks = 0; ks < 4; ks++) {
            uint32_t bh[8], bl[8];
            ldsm4(bh,     bhB + offB0 + ks * 32);
            ldsm4(bh + 4, bhB + offB1 + ks * 32);
            ldsm4(bl,     blB + offB0 + ks * 32);
            ldsm4(bl + 4, blB + offB1 + ks * 32);
            #pragma unroll
            for (int ti = 0; ti < 2; ti++) {
                uint32_t pa = aBase + (((wid * 32 + ti * 16 + g4) * AFP) + ks * 16 + t2) * 4;
                float2 x0 = ldsf2(pa);
                float2 x1 = ldsf2(pa + 8 * AFP * 4);
                float2 x2 = ldsf2(pa + 32);
                float2 x3 = ldsf2(pa + 8 * AFP * 4 + 32);
                uint32_t ah[4], al[4];
                split2(x0, ah[0], al[0]);
                split2(x1, ah[1], al[1]);
                split2(x2, ah[2], al[2]);
                split2(x3, ah[3], al[3]);
                #pragma unroll
                for (int j = 0; j < 4; j++) {
                    mma16816(acc[ti][j], ah, bh[2 * j], bh[2 * j + 1]);
                    mma16816(acc[ti][j], ah, bl[2 * j], bl[2 * j + 1]);
                    mma16816(acc[ti][j], al, bh[2 * j], bh[2 * j + 1]);
                }
            }
        }
    };

    load_async(0, 0);
    for (int c = 0; c < NC; c++) {
        int buf = c & 1;
        if (c + 1 < NC) {
            load_async(c + 1, buf ^ 1);
            asm volatile("cp.async.wait_group 1;" ::: "memory");
        } else {
            asm volatile("cp.async.wait_group 0;" ::: "memory");
        }
        __syncthreads();
        compute(buf);
        __syncthreads();
    }

    // Epilogue: relu + direct store [t][m][n]
    const int cg = lane >> 2;
    const int tc = (lane & 3) * 2;
    #pragma unroll
    for (int ti = 0; ti < 2; ti++) {
        const long row0 = (long)t * NNODES + mb * 128 + wid * 32 + ti * 16 + cg;
        #pragma unroll
        for (int j = 0; j < 4; j++) {
            float2 v0, v1;
            v0.x = fmaxf(acc[ti][j][0], 0.f);
            v0.y = fmaxf(acc[ti][j][1], 0.f);
            v1.x = fmaxf(acc[ti][j][2], 0.f);
            v1.y = fmaxf(acc[ti][j][3], 0.f);
            *(float2*)(Out + row0 * CDIM + j * 8 + tc)       = v0;
            *(float2*)(Out + (row0 + 8) * CDIM + j * 8 + tc) = v1;
        }
    }
}

// ---------------------------------------------------------------------------
// Launch: prep_fold -> GRU (persistent, weights-in-smem) -> XQ -> AY
// ---------------------------------------------------------------------------
extern "C" void kernel_launch(void* const* d_in, const int* in_sizes, int n_in,
                              void* d_out, int out_size) {
    const float* A  = (const float*)d_in[0];   // [1,16,4096,4096]
    const float* X  = (const float*)d_in[1];   // [16,4096,256]
    const float* Q0 = (const float*)d_in[2];   // [256,32]
    const float* Wz = (const float*)d_in[3];
    const float* Uz = (const float*)d_in[4];
    const float* Wr = (const float*)d_in[5];
    const float* Ur = (const float*)d_in[6];
    const float* Wh = (const float*)d_in[7];
    const float* Uh = (const float*)d_in[8];
    float* out = (float*)d_out;                // [16,4096,32]

    void *pQh = nullptr, *pQl = nullptr, *pYh = nullptr, *pYl = nullptr;
    cudaGetSymbolAddress(&pQh, g_Qth);
    cudaGetSymbolAddress(&pQl, g_Qtl);
    cudaGetSymbolAddress(&pYh, g_Yth);
    cudaGetSymbolAddress(&pYl, g_Ytl);

    cudaFuncSetAttribute(gru_persist,
                         cudaFuncAttributeMaxDynamicSharedMemorySize, GRU_SMEM);
    cudaFuncSetAttribute(ay_mma,
                         cudaFuncAttributeMaxDynamicSharedMemorySize, SMEM_BYTES);

    // 1. Fold z/r gate weights
    prep_fold<<<RDIM * RDIM / 256, 256>>>(Wz, Uz, Wr, Ur);

    // 2. Evolve Q over 16 steps (32 persistent blocks, weights loaded once)
    gru_persist<<<GRU_NB, 256, GRU_SMEM>>>(Q0, Wh, Uh);

    // 3. Y_t = X_t @ Q_t (static-smem tensor kernel) -> Y^T bf16 hi/lo
    xq_mma<<<dim3(NNODES / 128, TSTEPS), 128>>>(
        X, (const unsigned short*)pQh, (const unsigned short*)pQl,
        (unsigned short*)pYh, (unsigned short*)pYl);

    // 4. out_t = relu(A_t @ Y_t) (cp.async tensor kernel)
    ay_mma<<<dim3(NNODES / 128, TSTEPS), 128, SMEM_BYTES>>>(
        A, (const unsigned short*)pYh, (const unsigned short*)pYl, out);
}